// round 1
// baseline (speedup 1.0000x reference)
#include <cuda_runtime.h>
#include <cuda_fp16.h>
#include <mma.h>
#include <cstdint>

using namespace nvcuda;

#define B_   4
#define N_   2048
#define E_   1024
#define H_   16
#define D_   64
#define HID_ 4096
#define M_   (B_*N_)   // 8192 rows

// ---------------- device scratch (static globals: allocation-free) ----------
__device__ __half g_h   [M_*E_];                 // LN1 out (fp16)
__device__ __half g_qkv [(size_t)M_*3*E_];       // QKV (fp16)
__device__ __half g_scores[(size_t)B_*H_*N_*N_]; // scores / softmax weights
__device__ __half g_attn[M_*E_];                 // attention context (fp16)
__device__ float  g_res1[M_*E_];                 // attn proj + x (fp32)
__device__ __half g_h2  [M_*E_];                 // LN2 out (fp16)
__device__ __half g_z   [(size_t)M_*HID_];       // gelu(h2@w0) (fp16)
__device__ __half g_wqkv[E_*3*E_];
__device__ __half g_wproj[E_*E_];
__device__ __half g_w0  [E_*HID_];
__device__ __half g_w1  [HID_*E_];
__device__ __half g_bqkv[3*E_];
__device__ __half g_bproj[E_];
__device__ __half g_b0  [HID_];
__device__ __half g_b1  [E_];

// ---------------- helpers ---------------------------------------------------
__device__ __forceinline__ void cp16(void* smem_dst, const void* gsrc) {
    unsigned d = (unsigned)__cvta_generic_to_shared(smem_dst);
    asm volatile("cp.async.cg.shared.global [%0], [%1], 16;\n" :: "r"(d), "l"(gsrc));
}
__device__ __forceinline__ void cp_commit() { asm volatile("cp.async.commit_group;\n"); }

// ---------------- elementwise cast fp32 -> fp16 ------------------------------
__global__ void cast_f2h(const float* __restrict__ in, __half* __restrict__ out, int n) {
    int stride = gridDim.x * blockDim.x;
    for (int i = blockIdx.x * blockDim.x + threadIdx.x; i < n; i += stride)
        out[i] = __float2half(in[i]);
}

// ---------------- LayerNorm (fp32 in, fp16 out), one block per row, E=1024 ---
__global__ __launch_bounds__(256) void ln_kernel(const float* __restrict__ x,
                                                 const float* __restrict__ gam,
                                                 const float* __restrict__ bet,
                                                 __half* __restrict__ out) {
    int row = blockIdx.x;
    int t = threadIdx.x;                       // 256 threads, 4 floats each
    const float4 v  = ((const float4*)(x + (size_t)row * E_))[t];
    float s  = v.x + v.y + v.z + v.w;
    float ss = v.x*v.x + v.y*v.y + v.z*v.z + v.w*v.w;

    __shared__ float r0[8], r1[8];
    int w = t >> 5, l = t & 31;
    #pragma unroll
    for (int o = 16; o; o >>= 1) {
        s  += __shfl_xor_sync(0xffffffffu, s,  o);
        ss += __shfl_xor_sync(0xffffffffu, ss, o);
    }
    if (l == 0) { r0[w] = s; r1[w] = ss; }
    __syncthreads();
    if (t < 32) {
        float a = (l < 8) ? r0[l] : 0.f;
        float b = (l < 8) ? r1[l] : 0.f;
        #pragma unroll
        for (int o = 4; o; o >>= 1) {
            a += __shfl_xor_sync(0xffffffffu, a, o);
            b += __shfl_xor_sync(0xffffffffu, b, o);
        }
        if (l == 0) { r0[0] = a; r1[0] = b; }
    }
    __syncthreads();
    float mu  = r0[0] * (1.0f / E_);
    float var = r1[0] * (1.0f / E_) - mu * mu;
    float rs  = rsqrtf(var + 1e-5f);

    const float4 gv = ((const float4*)gam)[t];
    const float4 bv = ((const float4*)bet)[t];
    __half* op = out + (size_t)row * E_ + t * 4;
    op[0] = __float2half((v.x - mu) * rs * gv.x + bv.x);
    op[1] = __float2half((v.y - mu) * rs * gv.y + bv.y);
    op[2] = __float2half((v.z - mu) * rs * gv.z + bv.z);
    op[3] = __float2half((v.w - mu) * rs * gv.w + bv.w);
}

// ---------------- softmax over last dim (in-place on fp16), len N_=2048 ------
__global__ __launch_bounds__(256) void softmax_kernel(__half* __restrict__ wts) {
    size_t row = blockIdx.x;
    __half* p = wts + row * (size_t)N_;
    int t = threadIdx.x, w = t >> 5, l = t & 31;

    float v[8];
    float mx = -3.0e38f;
    #pragma unroll
    for (int i = 0; i < 8; i++) { v[i] = __half2float(p[t + i * 256]); mx = fmaxf(mx, v[i]); }

    __shared__ float red[8];
    #pragma unroll
    for (int o = 16; o; o >>= 1) mx = fmaxf(mx, __shfl_xor_sync(0xffffffffu, mx, o));
    if (l == 0) red[w] = mx;
    __syncthreads();
    if (t < 32) {
        float a = (l < 8) ? red[l] : -3.0e38f;
        #pragma unroll
        for (int o = 4; o; o >>= 1) a = fmaxf(a, __shfl_xor_sync(0xffffffffu, a, o));
        if (l == 0) red[0] = a;
    }
    __syncthreads();
    mx = red[0];
    __syncthreads();   // all readers done before red is reused

    float sum = 0.f;
    #pragma unroll
    for (int i = 0; i < 8; i++) { v[i] = expf(v[i] - mx); sum += v[i]; }
    #pragma unroll
    for (int o = 16; o; o >>= 1) sum += __shfl_xor_sync(0xffffffffu, sum, o);
    if (l == 0) red[w] = sum;
    __syncthreads();
    if (t < 32) {
        float a = (l < 8) ? red[l] : 0.f;
        #pragma unroll
        for (int o = 4; o; o >>= 1) a += __shfl_xor_sync(0xffffffffu, a, o);
        if (l == 0) red[0] = a;
    }
    __syncthreads();
    float inv = 1.0f / red[0];
    #pragma unroll
    for (int i = 0; i < 8; i++) p[t + i * 256] = __float2half(v[i] * inv);
}

// ---------------- generic fp16 GEMM, BM=128, BK=32, tunable BN, epilogues ----
enum { EPI_F16 = 0, EPI_GELU = 1, EPI_RES = 2 };

template<int BN, int EPI>
__global__ __launch_bounds__(256) void gemm_f16(
    const __half* __restrict__ A, int lda,
    const __half* __restrict__ Bm, int ldb,
    const __half* __restrict__ bias,
    void* __restrict__ Cout, int ldc,
    const float* __restrict__ res,
    int K, int HH,
    long sAz, long sBb, long sBh, long sCb, long sCh)
{
    constexpr int BM = 128, BK = 32;
    constexpr int WN = BN / 2;     // 2 warp-cols, 4 warp-rows
    constexpr int BF = WN / 16;

    int z = blockIdx.z;
    A  += (long)z * sAz;
    Bm += (long)(z / HH) * sBb + (long)(z % HH) * sBh;
    long coff = (long)(z / HH) * sCb + (long)(z % HH) * sCh;

    __shared__ __align__(32) __half As[2][BM][48];
    __shared__ __align__(32) __half Bs[2][BK][BN + 16];

    int tid = threadIdx.x;
    int warpId = tid >> 5, lane = tid & 31;
    int wm = warpId & 3, wn = warpId >> 2;
    int rowBase = blockIdx.y * BM;
    int colBase = blockIdx.x * BN;

    wmma::fragment<wmma::accumulator, 16, 16, 16, float> acc[2][BF];
    #pragma unroll
    for (int i = 0; i < 2; i++)
        #pragma unroll
        for (int j = 0; j < BF; j++) wmma::fill_fragment(acc[i][j], 0.0f);

    auto loadA = [&](int buf, int k0) {
        #pragma unroll
        for (int i = 0; i < 2; i++) {
            int c = tid + i * 256;            // 512 chunks of 16B
            int r = c >> 2, c8 = (c & 3) * 8;
            cp16(&As[buf][r][c8], A + (long)(rowBase + r) * lda + k0 + c8);
        }
    };
    auto loadB = [&](int buf, int k0) {
        constexpr int BCH = BK * BN / 8;      // 16B chunks
        #pragma unroll
        for (int i = 0; i < BCH / 256; i++) {
            int c = tid + i * 256;
            int r = c / (BN / 8), c8 = (c % (BN / 8)) * 8;
            cp16(&Bs[buf][r][c8], Bm + (long)(k0 + r) * ldb + colBase + c8);
        }
    };

    int KT = K / BK;
    loadA(0, 0); loadB(0, 0); cp_commit();

    for (int it = 0; it < KT; ++it) {
        int cur = it & 1;
        if (it + 1 < KT) {
            loadA(cur ^ 1, (it + 1) * BK);
            loadB(cur ^ 1, (it + 1) * BK);
            cp_commit();
            asm volatile("cp.async.wait_group 1;\n");
        } else {
            asm volatile("cp.async.wait_group 0;\n");
        }
        __syncthreads();
        #pragma unroll
        for (int kf = 0; kf < 2; kf++) {
            wmma::fragment<wmma::matrix_a, 16, 16, 16, __half, wmma::row_major> af[2];
            wmma::fragment<wmma::matrix_b, 16, 16, 16, __half, wmma::row_major> bf[BF];
            #pragma unroll
            for (int i = 0; i < 2; i++)
                wmma::load_matrix_sync(af[i], &As[cur][wm * 32 + i * 16][kf * 16], 48);
            #pragma unroll
            for (int j = 0; j < BF; j++)
                wmma::load_matrix_sync(bf[j], &Bs[cur][kf * 16][wn * WN + j * 16], BN + 16);
            #pragma unroll
            for (int i = 0; i < 2; i++)
                #pragma unroll
                for (int j = 0; j < BF; j++)
                    wmma::mma_sync(acc[i][j], af[i], bf[j], acc[i][j]);
        }
        __syncthreads();
    }

    // epilogue: per-warp 16x16 f32 scratch aliased onto As (loop ends w/ sync)
    float* sc = reinterpret_cast<float*>(&As[0][0][0]) + warpId * 256;
    #pragma unroll
    for (int i = 0; i < 2; i++) {
        #pragma unroll
        for (int j = 0; j < BF; j++) {
            wmma::store_matrix_sync(sc, acc[i][j], 16, wmma::mem_row_major);
            __syncwarp();
            int gr0 = rowBase + wm * 32 + i * 16;
            int gc0 = colBase + wn * WN + j * 16;
            #pragma unroll
            for (int e = 0; e < 8; e++) {
                int idx = lane * 8 + e;
                int r = idx >> 4, c = idx & 15;
                int gr = gr0 + r, gc = gc0 + c;
                float v = sc[idx];
                if (bias) v += __half2float(bias[gc]);
                long o = coff + (long)gr * ldc + gc;
                if (EPI == EPI_F16) {
                    ((__half*)Cout)[o] = __float2half(v);
                } else if (EPI == EPI_GELU) {
                    float f = __half2float(__float2half(v));   // round like fp16 pipeline
                    float g = 0.5f * f * (1.0f + erff(f * 0.70710678118654752f));
                    ((__half*)Cout)[o] = __float2half(g);
                } else { // EPI_RES: fp32 out = fp16(acc+bias) + residual
                    float f = __half2float(__float2half(v));
                    ((float*)Cout)[o] = f + res[(long)gr * ldc + gc];
                }
            }
            __syncwarp();
        }
    }
}

// ---------------- attention scores: S[z] = Q[z] @ K[z]^T  (K=D=64) ----------
__global__ __launch_bounds__(128) void attn_scores_kernel(
    const __half* __restrict__ qkv, __half* __restrict__ scores)
{
    int z = blockIdx.z;
    int b = z >> 4, h = z & 15;
    const __half* qb = qkv + (long)b * N_ * 3 * E_ + h * D_;
    const __half* kb = qb + E_;

    int tid = threadIdx.x;
    int warpId = tid >> 5, lane = tid & 31;
    int wm = warpId & 1, wn = warpId >> 1;    // 2x2 warps; 64x64 block tile
    int rowBase = blockIdx.y * 64 + wm * 32;
    int colBase = blockIdx.x * 64 + wn * 32;

    wmma::fragment<wmma::accumulator, 16, 16, 16, float> acc[2][2];
    #pragma unroll
    for (int i = 0; i < 2; i++)
        #pragma unroll
        for (int j = 0; j < 2; j++) wmma::fill_fragment(acc[i][j], 0.0f);

    #pragma unroll
    for (int kd = 0; kd < 4; kd++) {
        wmma::fragment<wmma::matrix_a, 16, 16, 16, __half, wmma::row_major> af[2];
        wmma::fragment<wmma::matrix_b, 16, 16, 16, __half, wmma::col_major> bf[2];
        #pragma unroll
        for (int i = 0; i < 2; i++)
            wmma::load_matrix_sync(af[i], qb + (long)(rowBase + i * 16) * (3 * E_) + kd * 16, 3 * E_);
        #pragma unroll
        for (int j = 0; j < 2; j++)
            wmma::load_matrix_sync(bf[j], kb + (long)(colBase + j * 16) * (3 * E_) + kd * 16, 3 * E_);
        #pragma unroll
        for (int i = 0; i < 2; i++)
            #pragma unroll
            for (int j = 0; j < 2; j++)
                wmma::mma_sync(acc[i][j], af[i], bf[j], acc[i][j]);
    }

    __shared__ __align__(32) float sscr[4][256];
    float* sc = sscr[warpId];
    __half* out = scores + (long)z * N_ * N_;
    #pragma unroll
    for (int i = 0; i < 2; i++)
        #pragma unroll
        for (int j = 0; j < 2; j++) {
            wmma::store_matrix_sync(sc, acc[i][j], 16, wmma::mem_row_major);
            __syncwarp();
            #pragma unroll
            for (int e = 0; e < 8; e++) {
                int idx = lane * 8 + e;
                int r = idx >> 4, c = idx & 15;
                out[(long)(rowBase + i * 16 + r) * N_ + colBase + j * 16 + c] = __float2half(sc[idx]);
            }
            __syncwarp();
        }
}

// ---------------- launch ----------------------------------------------------
extern "C" void kernel_launch(void* const* d_in, const int* in_sizes, int n_in,
                              void* d_out, int out_size)
{
    const float* x      = (const float*)d_in[0];
    const float* ln1_g  = (const float*)d_in[1];
    const float* ln1_b  = (const float*)d_in[2];
    const float* wqkv   = (const float*)d_in[3];
    const float* bqkv   = (const float*)d_in[4];
    const float* wproj  = (const float*)d_in[5];
    const float* bproj  = (const float*)d_in[6];
    const float* ln2_g  = (const float*)d_in[7];
    const float* ln2_b  = (const float*)d_in[8];
    const float* w0     = (const float*)d_in[9];
    const float* b0     = (const float*)d_in[10];
    const float* w1     = (const float*)d_in[11];
    const float* b1     = (const float*)d_in[12];

    void *p_h, *p_qkv, *p_scores, *p_attn, *p_res1, *p_h2, *p_z;
    void *p_wqkv, *p_wproj, *p_w0, *p_w1, *p_bqkv, *p_bproj, *p_b0, *p_b1;
    cudaGetSymbolAddress(&p_h, g_h);
    cudaGetSymbolAddress(&p_qkv, g_qkv);
    cudaGetSymbolAddress(&p_scores, g_scores);
    cudaGetSymbolAddress(&p_attn, g_attn);
    cudaGetSymbolAddress(&p_res1, g_res1);
    cudaGetSymbolAddress(&p_h2, g_h2);
    cudaGetSymbolAddress(&p_z, g_z);
    cudaGetSymbolAddress(&p_wqkv, g_wqkv);
    cudaGetSymbolAddress(&p_wproj, g_wproj);
    cudaGetSymbolAddress(&p_w0, g_w0);
    cudaGetSymbolAddress(&p_w1, g_w1);
    cudaGetSymbolAddress(&p_bqkv, g_bqkv);
    cudaGetSymbolAddress(&p_bproj, g_bproj);
    cudaGetSymbolAddress(&p_b0, g_b0);
    cudaGetSymbolAddress(&p_b1, g_b1);

    auto cast = [&](const float* src, void* dst, int n) {
        int blocks = (n + 255) / 256;
        if (blocks > 4096) blocks = 4096;
        cast_f2h<<<blocks, 256>>>(src, (__half*)dst, n);
    };
    cast(wqkv,  p_wqkv,  E_ * 3 * E_);
    cast(bqkv,  p_bqkv,  3 * E_);
    cast(wproj, p_wproj, E_ * E_);
    cast(bproj, p_bproj, E_);
    cast(w0,    p_w0,    E_ * HID_);
    cast(b0,    p_b0,    HID_);
    cast(w1,    p_w1,    HID_ * E_);
    cast(b1,    p_b1,    E_);

    // LN1
    ln_kernel<<<M_, 256>>>(x, ln1_g, ln1_b, (__half*)p_h);

    // QKV: [8192,1024] @ [1024,3072]
    gemm_f16<128, EPI_F16><<<dim3(3 * E_ / 128, M_ / 128, 1), 256>>>(
        (const __half*)p_h, E_, (const __half*)p_wqkv, 3 * E_,
        (const __half*)p_bqkv, p_qkv, 3 * E_, nullptr, E_, 1, 0, 0, 0, 0, 0);

    // scores = Q K^T per (b,h)
    attn_scores_kernel<<<dim3(N_ / 64, N_ / 64, B_ * H_), 128>>>(
        (const __half*)p_qkv, (__half*)p_scores);

    // softmax rows
    softmax_kernel<<<B_ * H_ * N_, 256>>>((__half*)p_scores);

    // O = W @ V per (b,h): [2048,2048]@[2048,64] -> write head-interleaved
    gemm_f16<64, EPI_F16><<<dim3(1, N_ / 128, B_ * H_), 256>>>(
        (const __half*)p_scores, N_,
        (const __half*)p_qkv + 2 * E_, 3 * E_,
        nullptr, p_attn, E_, nullptr, N_, H_,
        (long)N_ * N_, (long)N_ * 3 * E_, (long)D_, (long)N_ * E_, (long)D_);

    // proj + residual (fp32 out): res1 = fp16(attn@wproj + bproj) + x
    gemm_f16<128, EPI_RES><<<dim3(E_ / 128, M_ / 128, 1), 256>>>(
        (const __half*)p_attn, E_, (const __half*)p_wproj, E_,
        (const __half*)p_bproj, p_res1, E_, x, E_, 1, 0, 0, 0, 0, 0);

    // LN2
    ln_kernel<<<M_, 256>>>((const float*)p_res1, ln2_g, ln2_b, (__half*)p_h2);

    // MLP up + gelu: z = gelu(h2 @ w0 + b0)
    gemm_f16<128, EPI_GELU><<<dim3(HID_ / 128, M_ / 128, 1), 256>>>(
        (const __half*)p_h2, E_, (const __half*)p_w0, HID_,
        (const __half*)p_b0, p_z, HID_, nullptr, E_, 1, 0, 0, 0, 0, 0);

    // MLP down + residual (fp32 out): out = fp16(z @ w1 + b1) + res1
    gemm_f16<128, EPI_RES><<<dim3(E_ / 128, M_ / 128, 1), 256>>>(
        (const __half*)p_z, HID_, (const __half*)p_w1, E_,
        (const __half*)p_b1, d_out, E_, (const float*)p_res1, HID_, 1, 0, 0, 0, 0, 0);
}

// round 3
// speedup vs baseline: 2.6113x; 2.6113x over previous
#include <cuda_runtime.h>
#include <cuda_fp16.h>
#include <mma.h>
#include <cstdint>

using namespace nvcuda;

#define B_   4
#define N_   2048
#define E_   1024
#define H_   16
#define D_   64
#define HID_ 4096
#define M_   (B_*N_)   // 8192 rows

// ---------------- device scratch (static globals: allocation-free) ----------
__device__ __half g_h   [M_*E_];                 // LN1 out (fp16)
__device__ __half g_qkv [(size_t)M_*3*E_];       // QKV (fp16)
__device__ __half g_attn[M_*E_];                 // attention context (fp16)
__device__ float  g_res1[M_*E_];                 // attn proj + x (fp32)
__device__ __half g_h2  [M_*E_];                 // LN2 out (fp16)
__device__ __half g_z   [(size_t)M_*HID_];       // gelu(h2@w0) (fp16)
__device__ __half g_wqkv[E_*3*E_];
__device__ __half g_wproj[E_*E_];
__device__ __half g_w0  [E_*HID_];
__device__ __half g_w1  [HID_*E_];
__device__ __half g_bqkv[3*E_];
__device__ __half g_bproj[E_];
__device__ __half g_b0  [HID_];
__device__ __half g_b1  [E_];

// ---------------- helpers ---------------------------------------------------
__device__ __forceinline__ void cp16(void* smem_dst, const void* gsrc) {
    unsigned d = (unsigned)__cvta_generic_to_shared(smem_dst);
    asm volatile("cp.async.cg.shared.global [%0], [%1], 16;\n" :: "r"(d), "l"(gsrc));
}
__device__ __forceinline__ void cp16s(unsigned smem_dst, const void* gsrc) {
    asm volatile("cp.async.cg.shared.global [%0], [%1], 16;\n" :: "r"(smem_dst), "l"(gsrc));
}
__device__ __forceinline__ void cp_commit() { asm volatile("cp.async.commit_group;\n"); }

__device__ __forceinline__ void ldmx4(uint32_t addr, uint32_t& r0, uint32_t& r1, uint32_t& r2, uint32_t& r3) {
    asm volatile("ldmatrix.sync.aligned.m8n8.x4.shared.b16 {%0,%1,%2,%3}, [%4];\n"
                 : "=r"(r0), "=r"(r1), "=r"(r2), "=r"(r3) : "r"(addr));
}
__device__ __forceinline__ void ldmx4t(uint32_t addr, uint32_t& r0, uint32_t& r1, uint32_t& r2, uint32_t& r3) {
    asm volatile("ldmatrix.sync.aligned.m8n8.x4.trans.shared.b16 {%0,%1,%2,%3}, [%4];\n"
                 : "=r"(r0), "=r"(r1), "=r"(r2), "=r"(r3) : "r"(addr));
}
__device__ __forceinline__ void mma16816(float* c, const uint32_t* a, uint32_t b0, uint32_t b1) {
    asm volatile("mma.sync.aligned.m16n8k16.row.col.f32.f16.f16.f32 "
                 "{%0,%1,%2,%3},{%4,%5,%6,%7},{%8,%9},{%0,%1,%2,%3};\n"
                 : "+f"(c[0]), "+f"(c[1]), "+f"(c[2]), "+f"(c[3])
                 : "r"(a[0]), "r"(a[1]), "r"(a[2]), "r"(a[3]), "r"(b0), "r"(b1));
}

// ---------------- elementwise cast fp32 -> fp16 ------------------------------
__global__ void cast_f2h(const float* __restrict__ in, __half* __restrict__ out, int n) {
    int stride = gridDim.x * blockDim.x;
    for (int i = blockIdx.x * blockDim.x + threadIdx.x; i < n; i += stride)
        out[i] = __float2half(in[i]);
}

// ---------------- LayerNorm (fp32 in, fp16 out), one block per row, E=1024 ---
__global__ __launch_bounds__(256) void ln_kernel(const float* __restrict__ x,
                                                 const float* __restrict__ gam,
                                                 const float* __restrict__ bet,
                                                 __half* __restrict__ out) {
    int row = blockIdx.x;
    int t = threadIdx.x;                       // 256 threads, 4 floats each
    const float4 v  = ((const float4*)(x + (size_t)row * E_))[t];
    float s  = v.x + v.y + v.z + v.w;
    float ss = v.x*v.x + v.y*v.y + v.z*v.z + v.w*v.w;

    __shared__ float r0[8], r1[8];
    int w = t >> 5, l = t & 31;
    #pragma unroll
    for (int o = 16; o; o >>= 1) {
        s  += __shfl_xor_sync(0xffffffffu, s,  o);
        ss += __shfl_xor_sync(0xffffffffu, ss, o);
    }
    if (l == 0) { r0[w] = s; r1[w] = ss; }
    __syncthreads();
    if (t < 32) {
        float a = (l < 8) ? r0[l] : 0.f;
        float b = (l < 8) ? r1[l] : 0.f;
        #pragma unroll
        for (int o = 4; o; o >>= 1) {
            a += __shfl_xor_sync(0xffffffffu, a, o);
            b += __shfl_xor_sync(0xffffffffu, b, o);
        }
        if (l == 0) { r0[0] = a; r1[0] = b; }
    }
    __syncthreads();
    float mu  = r0[0] * (1.0f / E_);
    float var = r1[0] * (1.0f / E_) - mu * mu;
    float rs  = rsqrtf(var + 1e-5f);

    const float4 gv = ((const float4*)gam)[t];
    const float4 bv = ((const float4*)bet)[t];
    __half* op = out + (size_t)row * E_ + t * 4;
    op[0] = __float2half((v.x - mu) * rs * gv.x + bv.x);
    op[1] = __float2half((v.y - mu) * rs * gv.y + bv.y);
    op[2] = __float2half((v.z - mu) * rs * gv.z + bv.z);
    op[3] = __float2half((v.w - mu) * rs * gv.w + bv.w);
}

// ---------------- fused flash attention --------------------------------------
// Per CTA: 128 Q rows of one (b,h). 8 warps x 16 rows. KV streamed in 64-chunks.
// S = Q K^T (fp32 acc, rounded to fp16 to match reference scores tensor),
// online softmax (fp32 stats), P (fp16) @ V accumulated fp32, final /l.
__global__ __launch_bounds__(256) void flash_attn_kernel(
    const __half* __restrict__ qkv, __half* __restrict__ outp)
{
    __shared__ __align__(128) __half Qs[128 * 64];
    __shared__ __align__(128) __half Ks[2][64 * 64];
    __shared__ __align__(128) __half Vs[2][64 * 64];

    const int z = blockIdx.y;
    const int b = z >> 4, h = z & 15;
    const __half* qb = qkv + (size_t)b * N_ * 3 * E_ + h * D_;
    const __half* kb = qb + E_;
    const __half* vb = qb + 2 * E_;
    const int q0 = blockIdx.x * 128;

    const int tid = threadIdx.x;
    const int warp = tid >> 5, lane = tid & 31;

    const uint32_t sQ = (uint32_t)__cvta_generic_to_shared(Qs);
    const uint32_t sK[2] = { (uint32_t)__cvta_generic_to_shared(Ks[0]),
                             (uint32_t)__cvta_generic_to_shared(Ks[1]) };
    const uint32_t sV[2] = { (uint32_t)__cvta_generic_to_shared(Vs[0]),
                             (uint32_t)__cvta_generic_to_shared(Vs[1]) };

    // byte offset inside a 64-col (128B-row) tile, swizzled per 16B chunk
    auto swz = [](int row, int col) -> uint32_t {
        return (uint32_t)(row * 128 + ((((col >> 3) ^ (row & 7)) << 4) | ((col & 7) * 2)));
    };

    // ---- async loads ----
    // Q: 128 rows x 128B = 1024 chunks
    #pragma unroll
    for (int i = 0; i < 4; i++) {
        int ch = tid + i * 256;
        int r = ch >> 3, c = ch & 7;
        cp16s(sQ + r * 128 + ((c ^ (r & 7)) << 4),
              qb + (size_t)(q0 + r) * (3 * E_) + c * 8);
    }
    auto loadKV = [&](int buf, int kv0) {
        #pragma unroll
        for (int i = 0; i < 2; i++) {
            int ch = tid + i * 256;
            int r = ch >> 3, c = ch & 7;
            uint32_t off = r * 128 + ((c ^ (r & 7)) << 4);
            cp16s(sK[buf] + off, kb + (size_t)(kv0 + r) * (3 * E_) + c * 8);
            cp16s(sV[buf] + off, vb + (size_t)(kv0 + r) * (3 * E_) + c * 8);
        }
    };
    loadKV(0, 0);
    cp_commit();
    asm volatile("cp.async.wait_group 0;\n");
    __syncthreads();

    // ---- Q fragments (kept in registers for all iterations) ----
    uint32_t qf[4][4];
    {
        int r = warp * 16 + (lane & 7) + ((lane & 8) ? 8 : 0);
        int kc = ((lane & 16) ? 8 : 0);
        #pragma unroll
        for (int ks = 0; ks < 4; ks++)
            ldmx4(sQ + swz(r, ks * 16 + kc), qf[ks][0], qf[ks][1], qf[ks][2], qf[ks][3]);
    }

    // ---- running state ----
    float m0 = -1e30f, m1 = -1e30f;   // row maxima (two rows per lane)
    float l0 = 0.f, l1 = 0.f;         // row sums
    float oacc[8][4];
    #pragma unroll
    for (int j = 0; j < 8; j++)
        #pragma unroll
        for (int c = 0; c < 4; c++) oacc[j][c] = 0.f;

    const int ITERS = N_ / 64;
    for (int it = 0; it < ITERS; ++it) {
        int cur = it & 1;
        if (it + 1 < ITERS) {
            loadKV(cur ^ 1, (it + 1) * 64);
            cp_commit();
            asm volatile("cp.async.wait_group 1;\n");
        } else {
            asm volatile("cp.async.wait_group 0;\n");
        }
        __syncthreads();

        // ---- S = Q @ K^T  (per warp: 16 x 64 in 8 col-tiles) ----
        float sacc[8][4];
        #pragma unroll
        for (int j = 0; j < 8; j++)
            #pragma unroll
            for (int c = 0; c < 4; c++) sacc[j][c] = 0.f;

        const int g = lane >> 3;
        #pragma unroll
        for (int j2 = 0; j2 < 4; j2++) {
            int nr = j2 * 16 + ((g >> 1) << 3) + (lane & 7);
            #pragma unroll
            for (int ks = 0; ks < 4; ks++) {
                uint32_t b0, b1, b2, b3;
                ldmx4(sK[cur] + swz(nr, ks * 16 + ((g & 1) << 3)), b0, b1, b2, b3);
                mma16816(sacc[2 * j2],     qf[ks], b0, b1);
                mma16816(sacc[2 * j2 + 1], qf[ks], b2, b3);
            }
        }

        // ---- online softmax (rows r0 = lane>>2, r1 = r0+8) ----
        // round scores to fp16 (reference stores fp16 scores before softmax)
        float f0x[8], f0y[8], f1x[8], f1y[8];
        float mx0 = -1e30f, mx1 = -1e30f;
        #pragma unroll
        for (int j = 0; j < 8; j++) {
            __half2 h0 = __floats2half2_rn(sacc[j][0], sacc[j][1]);
            __half2 h1 = __floats2half2_rn(sacc[j][2], sacc[j][3]);
            float2 g0 = __half22float2(h0);
            float2 g1 = __half22float2(h1);
            f0x[j] = g0.x; f0y[j] = g0.y; f1x[j] = g1.x; f1y[j] = g1.y;
            mx0 = fmaxf(mx0, fmaxf(g0.x, g0.y));
            mx1 = fmaxf(mx1, fmaxf(g1.x, g1.y));
        }
        mx0 = fmaxf(mx0, __shfl_xor_sync(0xffffffffu, mx0, 1));
        mx0 = fmaxf(mx0, __shfl_xor_sync(0xffffffffu, mx0, 2));
        mx1 = fmaxf(mx1, __shfl_xor_sync(0xffffffffu, mx1, 1));
        mx1 = fmaxf(mx1, __shfl_xor_sync(0xffffffffu, mx1, 2));

        float m0n = fmaxf(m0, mx0), m1n = fmaxf(m1, mx1);
        float sc0 = __expf(m0 - m0n), sc1 = __expf(m1 - m1n);

        uint32_t pu0[8], pu1[8];
        float sum0 = 0.f, sum1 = 0.f;
        #pragma unroll
        for (int j = 0; j < 8; j++) {
            float p00 = __expf(f0x[j] - m0n), p01 = __expf(f0y[j] - m0n);
            float p10 = __expf(f1x[j] - m1n), p11 = __expf(f1y[j] - m1n);
            sum0 += p00 + p01;
            sum1 += p10 + p11;
            __half2 hp0 = __floats2half2_rn(p00, p01);
            __half2 hp1 = __floats2half2_rn(p10, p11);
            pu0[j] = *reinterpret_cast<uint32_t*>(&hp0);
            pu1[j] = *reinterpret_cast<uint32_t*>(&hp1);
        }
        sum0 += __shfl_xor_sync(0xffffffffu, sum0, 1);
        sum0 += __shfl_xor_sync(0xffffffffu, sum0, 2);
        sum1 += __shfl_xor_sync(0xffffffffu, sum1, 1);
        sum1 += __shfl_xor_sync(0xffffffffu, sum1, 2);

        l0 = l0 * sc0 + sum0;
        l1 = l1 * sc1 + sum1;
        m0 = m0n; m1 = m1n;

        #pragma unroll
        for (int j = 0; j < 8; j++) {
            oacc[j][0] *= sc0; oacc[j][1] *= sc0;
            oacc[j][2] *= sc1; oacc[j][3] *= sc1;
        }

        // ---- O += P @ V ----
        #pragma unroll
        for (int j2 = 0; j2 < 4; j2++) {
            int dc = j2 * 16 + ((g >> 1) << 3);
            #pragma unroll
            for (int kk = 0; kk < 4; kk++) {
                uint32_t b0, b1, b2, b3;
                ldmx4t(sV[cur] + swz(kk * 16 + ((g & 1) << 3) + (lane & 7), dc), b0, b1, b2, b3);
                uint32_t a[4] = { pu0[2 * kk], pu1[2 * kk], pu0[2 * kk + 1], pu1[2 * kk + 1] };
                mma16816(oacc[2 * j2],     a, b0, b1);
                mma16816(oacc[2 * j2 + 1], a, b2, b3);
            }
        }
        __syncthreads();
    }

    // ---- write out: O / l, fp16, layout [b, n, h*64 + d] ----
    float inv0 = 1.0f / l0, inv1 = 1.0f / l1;
    int r0g = q0 + warp * 16 + (lane >> 2);
    int r1g = r0g + 8;
    __half* ob = outp + (size_t)b * N_ * E_ + h * 64 + (lane & 3) * 2;
    #pragma unroll
    for (int j = 0; j < 8; j++) {
        __half2 v0 = __floats2half2_rn(oacc[j][0] * inv0, oacc[j][1] * inv0);
        __half2 v1 = __floats2half2_rn(oacc[j][2] * inv1, oacc[j][3] * inv1);
        *reinterpret_cast<__half2*>(ob + (size_t)r0g * E_ + j * 8) = v0;
        *reinterpret_cast<__half2*>(ob + (size_t)r1g * E_ + j * 8) = v1;
    }
}

// ---------------- generic fp16 GEMM, BM=128, BK=32, BN=128, epilogues --------
enum { EPI_F16 = 0, EPI_GELU = 1, EPI_RES = 2 };

template<int BN, int EPI>
__global__ __launch_bounds__(256) void gemm_f16(
    const __half* __restrict__ A, int lda,
    const __half* __restrict__ Bm, int ldb,
    const __half* __restrict__ bias,
    void* __restrict__ Cout, int ldc,
    const float* __restrict__ res,
    int K)
{
    constexpr int BM = 128, BK = 32;
    constexpr int WN = BN / 2;     // 2 warp-cols, 4 warp-rows
    constexpr int BF = WN / 16;

    __shared__ __align__(32) __half As[2][BM][48];
    __shared__ __align__(32) __half Bs[2][BK][BN + 16];

    int tid = threadIdx.x;
    int warpId = tid >> 5, lane = tid & 31;
    int wm = warpId & 3, wn = warpId >> 2;
    int rowBase = blockIdx.y * BM;
    int colBase = blockIdx.x * BN;

    wmma::fragment<wmma::accumulator, 16, 16, 16, float> acc[2][BF];
    #pragma unroll
    for (int i = 0; i < 2; i++)
        #pragma unroll
        for (int j = 0; j < BF; j++) wmma::fill_fragment(acc[i][j], 0.0f);

    auto loadA = [&](int buf, int k0) {
        #pragma unroll
        for (int i = 0; i < 2; i++) {
            int c = tid + i * 256;            // 512 chunks of 16B
            int r = c >> 2, c8 = (c & 3) * 8;
            cp16(&As[buf][r][c8], A + (long)(rowBase + r) * lda + k0 + c8);
        }
    };
    auto loadB = [&](int buf, int k0) {
        constexpr int BCH = BK * BN / 8;      // 16B chunks
        #pragma unroll
        for (int i = 0; i < BCH / 256; i++) {
            int c = tid + i * 256;
            int r = c / (BN / 8), c8 = (c % (BN / 8)) * 8;
            cp16(&Bs[buf][r][c8], Bm + (long)(k0 + r) * ldb + colBase + c8);
        }
    };

    int KT = K / BK;
    loadA(0, 0); loadB(0, 0); cp_commit();

    for (int it = 0; it < KT; ++it) {
        int cur = it & 1;
        if (it + 1 < KT) {
            loadA(cur ^ 1, (it + 1) * BK);
            loadB(cur ^ 1, (it + 1) * BK);
            cp_commit();
            asm volatile("cp.async.wait_group 1;\n");
        } else {
            asm volatile("cp.async.wait_group 0;\n");
        }
        __syncthreads();
        #pragma unroll
        for (int kf = 0; kf < 2; kf++) {
            wmma::fragment<wmma::matrix_a, 16, 16, 16, __half, wmma::row_major> af[2];
            wmma::fragment<wmma::matrix_b, 16, 16, 16, __half, wmma::row_major> bf[BF];
            #pragma unroll
            for (int i = 0; i < 2; i++)
                wmma::load_matrix_sync(af[i], &As[cur][wm * 32 + i * 16][kf * 16], 48);
            #pragma unroll
            for (int j = 0; j < BF; j++)
                wmma::load_matrix_sync(bf[j], &Bs[cur][kf * 16][wn * WN + j * 16], BN + 16);
            #pragma unroll
            for (int i = 0; i < 2; i++)
                #pragma unroll
                for (int j = 0; j < BF; j++)
                    wmma::mma_sync(acc[i][j], af[i], bf[j], acc[i][j]);
        }
        __syncthreads();
    }

    // epilogue: per-warp 16x16 f32 scratch aliased onto As; vectorized stores
    float* sc = reinterpret_cast<float*>(&As[0][0][0]) + warpId * 256;
    int fr = lane >> 1;                 // row within 16x16 tile (2 lanes/row)
    int fc = (lane & 1) * 8;            // col base, 8 consecutive elements
    #pragma unroll
    for (int i = 0; i < 2; i++) {
        #pragma unroll
        for (int j = 0; j < BF; j++) {
            wmma::store_matrix_sync(sc, acc[i][j], 16, wmma::mem_row_major);
            __syncwarp();
            int gr = rowBase + wm * 32 + i * 16 + fr;
            int gc = colBase + wn * WN + j * 16 + fc;
            float4 v0 = *reinterpret_cast<float4*>(sc + fr * 16 + fc);
            float4 v1 = *reinterpret_cast<float4*>(sc + fr * 16 + fc + 4);
            float v[8] = { v0.x, v0.y, v0.z, v0.w, v1.x, v1.y, v1.z, v1.w };
            if (bias) {
                #pragma unroll
                for (int e = 0; e < 8; e++) v[e] += __half2float(bias[gc + e]);
            }
            long o = (long)gr * ldc + gc;
            if (EPI == EPI_F16) {
                alignas(16) __half hv[8];
                #pragma unroll
                for (int e = 0; e < 8; e++) hv[e] = __float2half(v[e]);
                *reinterpret_cast<uint4*>((__half*)Cout + o) = *reinterpret_cast<uint4*>(hv);
            } else if (EPI == EPI_GELU) {
                alignas(16) __half hv[8];
                #pragma unroll
                for (int e = 0; e < 8; e++) {
                    float f = __half2float(__float2half(v[e]));  // round like fp16 pipeline
                    float gl = 0.5f * f * (1.0f + erff(f * 0.70710678118654752f));
                    hv[e] = __float2half(gl);
                }
                *reinterpret_cast<uint4*>((__half*)Cout + o) = *reinterpret_cast<uint4*>(hv);
            } else { // EPI_RES: fp32 out = fp16(acc+bias) + residual
                const float* rp = res + (long)gr * ldc + gc;
                float4 r0 = *reinterpret_cast<const float4*>(rp);
                float4 r1 = *reinterpret_cast<const float4*>(rp + 4);
                float4 w0v, w1v;
                w0v.x = __half2float(__float2half(v[0])) + r0.x;
                w0v.y = __half2float(__float2half(v[1])) + r0.y;
                w0v.z = __half2float(__float2half(v[2])) + r0.z;
                w0v.w = __half2float(__float2half(v[3])) + r0.w;
                w1v.x = __half2float(__float2half(v[4])) + r1.x;
                w1v.y = __half2float(__float2half(v[5])) + r1.y;
                w1v.z = __half2float(__float2half(v[6])) + r1.z;
                w1v.w = __half2float(__float2half(v[7])) + r1.w;
                *reinterpret_cast<float4*>((float*)Cout + o) = w0v;
                *reinterpret_cast<float4*>((float*)Cout + o + 4) = w1v;
            }
            __syncwarp();
        }
    }
}

// ---------------- launch ----------------------------------------------------
extern "C" void kernel_launch(void* const* d_in, const int* in_sizes, int n_in,
                              void* d_out, int out_size)
{
    const float* x      = (const float*)d_in[0];
    const float* ln1_g  = (const float*)d_in[1];
    const float* ln1_b  = (const float*)d_in[2];
    const float* wqkv   = (const float*)d_in[3];
    const float* bqkv   = (const float*)d_in[4];
    const float* wproj  = (const float*)d_in[5];
    const float* bproj  = (const float*)d_in[6];
    const float* ln2_g  = (const float*)d_in[7];
    const float* ln2_b  = (const float*)d_in[8];
    const float* w0     = (const float*)d_in[9];
    const float* b0     = (const float*)d_in[10];
    const float* w1     = (const float*)d_in[11];
    const float* b1     = (const float*)d_in[12];

    void *p_h, *p_qkv, *p_attn, *p_res1, *p_h2, *p_z;
    void *p_wqkv, *p_wproj, *p_w0, *p_w1, *p_bqkv, *p_bproj, *p_b0, *p_b1;
    cudaGetSymbolAddress(&p_h, g_h);
    cudaGetSymbolAddress(&p_qkv, g_qkv);
    cudaGetSymbolAddress(&p_attn, g_attn);
    cudaGetSymbolAddress(&p_res1, g_res1);
    cudaGetSymbolAddress(&p_h2, g_h2);
    cudaGetSymbolAddress(&p_z, g_z);
    cudaGetSymbolAddress(&p_wqkv, g_wqkv);
    cudaGetSymbolAddress(&p_wproj, g_wproj);
    cudaGetSymbolAddress(&p_w0, g_w0);
    cudaGetSymbolAddress(&p_w1, g_w1);
    cudaGetSymbolAddress(&p_bqkv, g_bqkv);
    cudaGetSymbolAddress(&p_bproj, g_bproj);
    cudaGetSymbolAddress(&p_b0, g_b0);
    cudaGetSymbolAddress(&p_b1, g_b1);

    auto cast = [&](const float* src, void* dst, int n) {
        int blocks = (n + 255) / 256;
        if (blocks > 4096) blocks = 4096;
        cast_f2h<<<blocks, 256>>>(src, (__half*)dst, n);
    };
    cast(wqkv,  p_wqkv,  E_ * 3 * E_);
    cast(bqkv,  p_bqkv,  3 * E_);
    cast(wproj, p_wproj, E_ * E_);
    cast(bproj, p_bproj, E_);
    cast(w0,    p_w0,    E_ * HID_);
    cast(b0,    p_b0,    HID_);
    cast(w1,    p_w1,    HID_ * E_);
    cast(b1,    p_b1,    E_);

    // LN1
    ln_kernel<<<M_, 256>>>(x, ln1_g, ln1_b, (__half*)p_h);

    // QKV: [8192,1024] @ [1024,3072]
    gemm_f16<128, EPI_F16><<<dim3(3 * E_ / 128, M_ / 128), 256>>>(
        (const __half*)p_h, E_, (const __half*)p_wqkv, 3 * E_,
        (const __half*)p_bqkv, p_qkv, 3 * E_, nullptr, E_);

    // fused flash attention: scores + softmax + PV, writes context fp16
    flash_attn_kernel<<<dim3(N_ / 128, B_ * H_), 256>>>(
        (const __half*)p_qkv, (__half*)p_attn);

    // proj + residual (fp32 out): res1 = fp16(attn@wproj + bproj) + x
    gemm_f16<128, EPI_RES><<<dim3(E_ / 128, M_ / 128), 256>>>(
        (const __half*)p_attn, E_, (const __half*)p_wproj, E_,
        (const __half*)p_bproj, p_res1, E_, x, E_);

    // LN2
    ln_kernel<<<M_, 256>>>((const float*)p_res1, ln2_g, ln2_b, (__half*)p_h2);

    // MLP up + gelu: z = gelu(h2 @ w0 + b0)
    gemm_f16<128, EPI_GELU><<<dim3(HID_ / 128, M_ / 128), 256>>>(
        (const __half*)p_h2, E_, (const __half*)p_w0, HID_,
        (const __half*)p_b0, p_z, HID_, nullptr, E_);

    // MLP down + residual (fp32 out): out = fp16(z @ w1 + b1) + res1
    gemm_f16<128, EPI_RES><<<dim3(E_ / 128, M_ / 128), 256>>>(
        (const __half*)p_z, HID_, (const __half*)p_w1, E_,
        (const __half*)p_b1, d_out, E_, (const float*)p_res1, HID_);
}

// round 4
// speedup vs baseline: 3.3519x; 1.2836x over previous
#include <cuda_runtime.h>
#include <cuda_fp16.h>
#include <cstdint>

#define B_   4
#define N_   2048
#define E_   1024
#define H_   16
#define D_   64
#define HID_ 4096
#define M_   (B_*N_)   // 8192 rows

// ---------------- device scratch (static globals: allocation-free) ----------
__device__ __half g_h   [M_*E_];                 // LN1 out (fp16)
__device__ __half g_qkv [(size_t)M_*3*E_];       // QKV (fp16)
__device__ __half g_attn[M_*E_];                 // attention context (fp16)
__device__ float  g_res1[M_*E_];                 // attn proj + x (fp32)
__device__ __half g_h2  [M_*E_];                 // LN2 out (fp16)
__device__ __half g_z   [(size_t)M_*HID_];       // gelu(h2@w0) (fp16)
__device__ __half g_wqkv[E_*3*E_];
__device__ __half g_wproj[E_*E_];
__device__ __half g_w0  [E_*HID_];
__device__ __half g_w1  [HID_*E_];
__device__ __half g_bqkv[3*E_];
__device__ __half g_bproj[E_];
__device__ __half g_b0  [HID_];
__device__ __half g_b1  [E_];

// ---------------- helpers ---------------------------------------------------
__device__ __forceinline__ void cp16s(unsigned smem_dst, const void* gsrc) {
    asm volatile("cp.async.cg.shared.global [%0], [%1], 16;\n" :: "r"(smem_dst), "l"(gsrc));
}
__device__ __forceinline__ void cp_commit() { asm volatile("cp.async.commit_group;\n"); }

__device__ __forceinline__ void ldmx4(uint32_t addr, uint32_t& r0, uint32_t& r1, uint32_t& r2, uint32_t& r3) {
    asm volatile("ldmatrix.sync.aligned.m8n8.x4.shared.b16 {%0,%1,%2,%3}, [%4];\n"
                 : "=r"(r0), "=r"(r1), "=r"(r2), "=r"(r3) : "r"(addr));
}
__device__ __forceinline__ void ldmx4t(uint32_t addr, uint32_t& r0, uint32_t& r1, uint32_t& r2, uint32_t& r3) {
    asm volatile("ldmatrix.sync.aligned.m8n8.x4.trans.shared.b16 {%0,%1,%2,%3}, [%4];\n"
                 : "=r"(r0), "=r"(r1), "=r"(r2), "=r"(r3) : "r"(addr));
}
__device__ __forceinline__ void mma16816(float* c, const uint32_t* a, uint32_t b0, uint32_t b1) {
    asm volatile("mma.sync.aligned.m16n8k16.row.col.f32.f16.f16.f32 "
                 "{%0,%1,%2,%3},{%4,%5,%6,%7},{%8,%9},{%0,%1,%2,%3};\n"
                 : "+f"(c[0]), "+f"(c[1]), "+f"(c[2]), "+f"(c[3])
                 : "r"(a[0]), "r"(a[1]), "r"(a[2]), "r"(a[3]), "r"(b0), "r"(b1));
}
// byte offset inside a 64-col (128B-row) half tile, swizzled per 16B chunk
__device__ __forceinline__ uint32_t swz(int row, int col) {
    return (uint32_t)(row * 128 + ((((col >> 3) ^ (row & 7)) << 4) | ((col & 7) * 2)));
}

// ---------------- elementwise cast fp32 -> fp16 ------------------------------
__global__ void cast_f2h(const float* __restrict__ in, __half* __restrict__ out, int n) {
    int stride = gridDim.x * blockDim.x;
    for (int i = blockIdx.x * blockDim.x + threadIdx.x; i < n; i += stride)
        out[i] = __float2half(in[i]);
}

// ---------------- LayerNorm (fp32 in, fp16 out), one block per row, E=1024 ---
__global__ __launch_bounds__(256) void ln_kernel(const float* __restrict__ x,
                                                 const float* __restrict__ gam,
                                                 const float* __restrict__ bet,
                                                 __half* __restrict__ out) {
    int row = blockIdx.x;
    int t = threadIdx.x;
    const float4 v  = ((const float4*)(x + (size_t)row * E_))[t];
    float s  = v.x + v.y + v.z + v.w;
    float ss = v.x*v.x + v.y*v.y + v.z*v.z + v.w*v.w;

    __shared__ float r0[8], r1[8];
    int w = t >> 5, l = t & 31;
    #pragma unroll
    for (int o = 16; o; o >>= 1) {
        s  += __shfl_xor_sync(0xffffffffu, s,  o);
        ss += __shfl_xor_sync(0xffffffffu, ss, o);
    }
    if (l == 0) { r0[w] = s; r1[w] = ss; }
    __syncthreads();
    if (t < 32) {
        float a = (l < 8) ? r0[l] : 0.f;
        float b = (l < 8) ? r1[l] : 0.f;
        #pragma unroll
        for (int o = 4; o; o >>= 1) {
            a += __shfl_xor_sync(0xffffffffu, a, o);
            b += __shfl_xor_sync(0xffffffffu, b, o);
        }
        if (l == 0) { r0[0] = a; r1[0] = b; }
    }
    __syncthreads();
    float mu  = r0[0] * (1.0f / E_);
    float var = r1[0] * (1.0f / E_) - mu * mu;
    float rs  = rsqrtf(var + 1e-5f);

    const float4 gv = ((const float4*)gam)[t];
    const float4 bv = ((const float4*)bet)[t];
    __half* op = out + (size_t)row * E_ + t * 4;
    op[0] = __float2half((v.x - mu) * rs * gv.x + bv.x);
    op[1] = __float2half((v.y - mu) * rs * gv.y + bv.y);
    op[2] = __float2half((v.z - mu) * rs * gv.z + bv.z);
    op[3] = __float2half((v.w - mu) * rs * gv.w + bv.w);
}

// ---------------- fused flash attention (validated round 3) ------------------
__global__ __launch_bounds__(256) void flash_attn_kernel(
    const __half* __restrict__ qkv, __half* __restrict__ outp)
{
    __shared__ __align__(128) __half Qs[128 * 64];
    __shared__ __align__(128) __half Ks[2][64 * 64];
    __shared__ __align__(128) __half Vs[2][64 * 64];

    const int z = blockIdx.y;
    const int b = z >> 4, h = z & 15;
    const __half* qb = qkv + (size_t)b * N_ * 3 * E_ + h * D_;
    const __half* kb = qb + E_;
    const __half* vb = qb + 2 * E_;
    const int q0 = blockIdx.x * 128;

    const int tid = threadIdx.x;
    const int warp = tid >> 5, lane = tid & 31;

    const uint32_t sQ = (uint32_t)__cvta_generic_to_shared(Qs);
    const uint32_t sK[2] = { (uint32_t)__cvta_generic_to_shared(Ks[0]),
                             (uint32_t)__cvta_generic_to_shared(Ks[1]) };
    const uint32_t sV[2] = { (uint32_t)__cvta_generic_to_shared(Vs[0]),
                             (uint32_t)__cvta_generic_to_shared(Vs[1]) };

    #pragma unroll
    for (int i = 0; i < 4; i++) {
        int ch = tid + i * 256;
        int r = ch >> 3, c = ch & 7;
        cp16s(sQ + r * 128 + ((c ^ (r & 7)) << 4),
              qb + (size_t)(q0 + r) * (3 * E_) + c * 8);
    }
    auto loadKV = [&](int buf, int kv0) {
        #pragma unroll
        for (int i = 0; i < 2; i++) {
            int ch = tid + i * 256;
            int r = ch >> 3, c = ch & 7;
            uint32_t off = r * 128 + ((c ^ (r & 7)) << 4);
            cp16s(sK[buf] + off, kb + (size_t)(kv0 + r) * (3 * E_) + c * 8);
            cp16s(sV[buf] + off, vb + (size_t)(kv0 + r) * (3 * E_) + c * 8);
        }
    };
    loadKV(0, 0);
    cp_commit();
    asm volatile("cp.async.wait_group 0;\n");
    __syncthreads();

    uint32_t qf[4][4];
    {
        int r = warp * 16 + (lane & 7) + ((lane & 8) ? 8 : 0);
        int kc = ((lane & 16) ? 8 : 0);
        #pragma unroll
        for (int ks = 0; ks < 4; ks++)
            ldmx4(sQ + swz(r, ks * 16 + kc), qf[ks][0], qf[ks][1], qf[ks][2], qf[ks][3]);
    }

    float m0 = -1e30f, m1 = -1e30f;
    float l0 = 0.f, l1 = 0.f;
    float oacc[8][4];
    #pragma unroll
    for (int j = 0; j < 8; j++)
        #pragma unroll
        for (int c = 0; c < 4; c++) oacc[j][c] = 0.f;

    const int ITERS = N_ / 64;
    for (int it = 0; it < ITERS; ++it) {
        int cur = it & 1;
        if (it + 1 < ITERS) {
            loadKV(cur ^ 1, (it + 1) * 64);
            cp_commit();
            asm volatile("cp.async.wait_group 1;\n");
        } else {
            asm volatile("cp.async.wait_group 0;\n");
        }
        __syncthreads();

        float sacc[8][4];
        #pragma unroll
        for (int j = 0; j < 8; j++)
            #pragma unroll
            for (int c = 0; c < 4; c++) sacc[j][c] = 0.f;

        const int g = lane >> 3;
        #pragma unroll
        for (int j2 = 0; j2 < 4; j2++) {
            int nr = j2 * 16 + ((g >> 1) << 3) + (lane & 7);
            #pragma unroll
            for (int ks = 0; ks < 4; ks++) {
                uint32_t b0, b1, b2, b3;
                ldmx4(sK[cur] + swz(nr, ks * 16 + ((g & 1) << 3)), b0, b1, b2, b3);
                mma16816(sacc[2 * j2],     qf[ks], b0, b1);
                mma16816(sacc[2 * j2 + 1], qf[ks], b2, b3);
            }
        }

        float f0x[8], f0y[8], f1x[8], f1y[8];
        float mx0 = -1e30f, mx1 = -1e30f;
        #pragma unroll
        for (int j = 0; j < 8; j++) {
            __half2 h0 = __floats2half2_rn(sacc[j][0], sacc[j][1]);
            __half2 h1 = __floats2half2_rn(sacc[j][2], sacc[j][3]);
            float2 g0 = __half22float2(h0);
            float2 g1 = __half22float2(h1);
            f0x[j] = g0.x; f0y[j] = g0.y; f1x[j] = g1.x; f1y[j] = g1.y;
            mx0 = fmaxf(mx0, fmaxf(g0.x, g0.y));
            mx1 = fmaxf(mx1, fmaxf(g1.x, g1.y));
        }
        mx0 = fmaxf(mx0, __shfl_xor_sync(0xffffffffu, mx0, 1));
        mx0 = fmaxf(mx0, __shfl_xor_sync(0xffffffffu, mx0, 2));
        mx1 = fmaxf(mx1, __shfl_xor_sync(0xffffffffu, mx1, 1));
        mx1 = fmaxf(mx1, __shfl_xor_sync(0xffffffffu, mx1, 2));

        float m0n = fmaxf(m0, mx0), m1n = fmaxf(m1, mx1);
        float sc0 = __expf(m0 - m0n), sc1 = __expf(m1 - m1n);

        uint32_t pu0[8], pu1[8];
        float sum0 = 0.f, sum1 = 0.f;
        #pragma unroll
        for (int j = 0; j < 8; j++) {
            float p00 = __expf(f0x[j] - m0n), p01 = __expf(f0y[j] - m0n);
            float p10 = __expf(f1x[j] - m1n), p11 = __expf(f1y[j] - m1n);
            sum0 += p00 + p01;
            sum1 += p10 + p11;
            __half2 hp0 = __floats2half2_rn(p00, p01);
            __half2 hp1 = __floats2half2_rn(p10, p11);
            pu0[j] = *reinterpret_cast<uint32_t*>(&hp0);
            pu1[j] = *reinterpret_cast<uint32_t*>(&hp1);
        }
        sum0 += __shfl_xor_sync(0xffffffffu, sum0, 1);
        sum0 += __shfl_xor_sync(0xffffffffu, sum0, 2);
        sum1 += __shfl_xor_sync(0xffffffffu, sum1, 1);
        sum1 += __shfl_xor_sync(0xffffffffu, sum1, 2);

        l0 = l0 * sc0 + sum0;
        l1 = l1 * sc1 + sum1;
        m0 = m0n; m1 = m1n;

        #pragma unroll
        for (int j = 0; j < 8; j++) {
            oacc[j][0] *= sc0; oacc[j][1] *= sc0;
            oacc[j][2] *= sc1; oacc[j][3] *= sc1;
        }

        #pragma unroll
        for (int j2 = 0; j2 < 4; j2++) {
            int dc = j2 * 16 + ((g >> 1) << 3);
            #pragma unroll
            for (int kk = 0; kk < 4; kk++) {
                uint32_t b0, b1, b2, b3;
                ldmx4t(sV[cur] + swz(kk * 16 + ((g & 1) << 3) + (lane & 7), dc), b0, b1, b2, b3);
                uint32_t a[4] = { pu0[2 * kk], pu1[2 * kk], pu0[2 * kk + 1], pu1[2 * kk + 1] };
                mma16816(oacc[2 * j2],     a, b0, b1);
                mma16816(oacc[2 * j2 + 1], a, b2, b3);
            }
        }
        __syncthreads();
    }

    float inv0 = 1.0f / l0, inv1 = 1.0f / l1;
    int r0g = q0 + warp * 16 + (lane >> 2);
    int r1g = r0g + 8;
    __half* ob = outp + (size_t)b * N_ * E_ + h * 64 + (lane & 3) * 2;
    #pragma unroll
    for (int j = 0; j < 8; j++) {
        __half2 v0 = __floats2half2_rn(oacc[j][0] * inv0, oacc[j][1] * inv0);
        __half2 v1 = __floats2half2_rn(oacc[j][2] * inv1, oacc[j][3] * inv1);
        *reinterpret_cast<__half2*>(ob + (size_t)r0g * E_ + j * 8) = v0;
        *reinterpret_cast<__half2*>(ob + (size_t)r1g * E_ + j * 8) = v1;
    }
}

// ---------------- fp16 GEMM v2: raw mma, swizzled smem, 3-stage pipeline -----
// BM=128, BN=128, BK=64, 256 thr, warp tile 64x32 (2x4 warps).
enum { EPI_F16 = 0, EPI_GELU = 1, EPI_RES = 2 };

template<int EPI>
__global__ __launch_bounds__(256) void gemm2(
    const __half* __restrict__ A, int lda,
    const __half* __restrict__ Bm, int ldb,
    const __half* __restrict__ bias,
    void* __restrict__ Cout, int ldc,
    const float* __restrict__ res, int K)
{
    extern __shared__ __align__(128) char dynsmem[];
    __half* As = (__half*)dynsmem;                    // 3 stages * 128x64
    __half* Bs = (__half*)(dynsmem + 3 * 16384);      // 3 stages * 64x128

    const int tid = threadIdx.x;
    const int warp = tid >> 5, lane = tid & 31;
    const int wm = warp & 1, wn = warp >> 1;          // 2 x 4 warp grid
    const int rowBase = blockIdx.y * 128;
    const int colBase = blockIdx.x * 128;

    const uint32_t sA = (uint32_t)__cvta_generic_to_shared(As);
    const uint32_t sB = (uint32_t)__cvta_generic_to_shared(Bs);

    auto loadA = [&](int stg, int k0) {
        #pragma unroll
        for (int i = 0; i < 4; i++) {
            int ch = tid + i * 256;                    // 1024 x 16B
            int r = ch >> 3, c = ch & 7;
            cp16s(sA + stg * 16384 + r * 128 + ((c ^ (r & 7)) << 4),
                  A + (size_t)(rowBase + r) * lda + k0 + c * 8);
        }
    };
    auto loadB = [&](int stg, int k0) {
        #pragma unroll
        for (int i = 0; i < 4; i++) {
            int ch = tid + i * 256;                    // 64 rows x 16 chunks
            int r = ch >> 4, c = ch & 15;
            cp16s(sB + stg * 16384 + (c >> 3) * 8192 + r * 128 + (((c & 7) ^ (r & 7)) << 4),
                  Bm + (size_t)(k0 + r) * ldb + colBase + c * 8);
        }
    };

    float acc[4][4][4];
    #pragma unroll
    for (int mi = 0; mi < 4; mi++)
        #pragma unroll
        for (int j = 0; j < 4; j++)
            #pragma unroll
            for (int c = 0; c < 4; c++) acc[mi][j][c] = 0.f;

    const int KT = K / 64;
    loadA(0, 0);  loadB(0, 0);  cp_commit();
    loadA(1, 64); loadB(1, 64); cp_commit();

    const int g = lane >> 3;
    for (int it = 0; it < KT; ++it) {
        asm volatile("cp.async.wait_group 1;\n");
        __syncthreads();
        // safe: stage (it+2)%3 was consumed at iter it-1, done before this barrier
        if (it + 2 < KT) { loadA((it + 2) % 3, (it + 2) * 64); loadB((it + 2) % 3, (it + 2) * 64); cp_commit(); }

        const uint32_t aoff = sA + (it % 3) * 16384;
        const uint32_t boff = sB + (it % 3) * 16384;
        #pragma unroll
        for (int ks = 0; ks < 4; ks++) {
            uint32_t bf[2][4];
            #pragma unroll
            for (int j = 0; j < 2; j++) {
                int nn = wn * 32 + j * 16 + ((g >> 1) << 3);
                uint32_t addr = boff + (nn >> 6) * 8192
                              + swz(ks * 16 + ((g & 1) << 3) + (lane & 7), nn & 63);
                ldmx4t(addr, bf[j][0], bf[j][1], bf[j][2], bf[j][3]);
            }
            #pragma unroll
            for (int mi = 0; mi < 4; mi++) {
                uint32_t af[4];
                int r = wm * 64 + mi * 16 + (lane & 15);
                ldmx4(aoff + swz(r, ks * 16 + ((lane >> 4) << 3)), af[0], af[1], af[2], af[3]);
                mma16816(acc[mi][0], af, bf[0][0], bf[0][1]);
                mma16816(acc[mi][1], af, bf[0][2], bf[0][3]);
                mma16816(acc[mi][2], af, bf[1][0], bf[1][1]);
                mma16816(acc[mi][3], af, bf[1][2], bf[1][3]);
            }
        }
    }

    // ---- direct register epilogue ----
    #pragma unroll
    for (int mi = 0; mi < 4; mi++) {
        int gr0 = rowBase + wm * 64 + mi * 16 + (lane >> 2);
        int gr1 = gr0 + 8;
        #pragma unroll
        for (int j = 0; j < 4; j++) {
            int gc = colBase + wn * 32 + j * 8 + (lane & 3) * 2;
            float b0 = 0.f, b1 = 0.f;
            if (bias) {
                __half2 hb = *reinterpret_cast<const __half2*>(bias + gc);
                float2 fb = __half22float2(hb);
                b0 = fb.x; b1 = fb.y;
            }
            float v0 = acc[mi][j][0] + b0, v1 = acc[mi][j][1] + b1;
            float v2 = acc[mi][j][2] + b0, v3 = acc[mi][j][3] + b1;
            size_t o0 = (size_t)gr0 * ldc + gc;
            size_t o1 = (size_t)gr1 * ldc + gc;
            if (EPI == EPI_F16) {
                *reinterpret_cast<__half2*>((__half*)Cout + o0) = __floats2half2_rn(v0, v1);
                *reinterpret_cast<__half2*>((__half*)Cout + o1) = __floats2half2_rn(v2, v3);
            } else if (EPI == EPI_GELU) {
                float f0 = __half2float(__float2half(v0));
                float f1 = __half2float(__float2half(v1));
                float f2 = __half2float(__float2half(v2));
                float f3 = __half2float(__float2half(v3));
                float g0 = 0.5f * f0 * (1.0f + erff(f0 * 0.70710678118654752f));
                float g1 = 0.5f * f1 * (1.0f + erff(f1 * 0.70710678118654752f));
                float g2 = 0.5f * f2 * (1.0f + erff(f2 * 0.70710678118654752f));
                float g3 = 0.5f * f3 * (1.0f + erff(f3 * 0.70710678118654752f));
                *reinterpret_cast<__half2*>((__half*)Cout + o0) = __floats2half2_rn(g0, g1);
                *reinterpret_cast<__half2*>((__half*)Cout + o1) = __floats2half2_rn(g2, g3);
            } else { // EPI_RES: fp32 out = fp16(acc+bias) + residual
                float2 r0v = *reinterpret_cast<const float2*>(res + o0);
                float2 r1v = *reinterpret_cast<const float2*>(res + o1);
                float2 w0v, w1v;
                w0v.x = __half2float(__float2half(v0)) + r0v.x;
                w0v.y = __half2float(__float2half(v1)) + r0v.y;
                w1v.x = __half2float(__float2half(v2)) + r1v.x;
                w1v.y = __half2float(__float2half(v3)) + r1v.y;
                *reinterpret_cast<float2*>((float*)Cout + o0) = w0v;
                *reinterpret_cast<float2*>((float*)Cout + o1) = w1v;
            }
        }
    }
}

// ---------------- launch ----------------------------------------------------
#define GEMM_SMEM (3 * 16384 * 2)

extern "C" void kernel_launch(void* const* d_in, const int* in_sizes, int n_in,
                              void* d_out, int out_size)
{
    const float* x      = (const float*)d_in[0];
    const float* ln1_g  = (const float*)d_in[1];
    const float* ln1_b  = (const float*)d_in[2];
    const float* wqkv   = (const float*)d_in[3];
    const float* bqkv   = (const float*)d_in[4];
    const float* wproj  = (const float*)d_in[5];
    const float* bproj  = (const float*)d_in[6];
    const float* ln2_g  = (const float*)d_in[7];
    const float* ln2_b  = (const float*)d_in[8];
    const float* w0     = (const float*)d_in[9];
    const float* b0     = (const float*)d_in[10];
    const float* w1     = (const float*)d_in[11];
    const float* b1     = (const float*)d_in[12];

    void *p_h, *p_qkv, *p_attn, *p_res1, *p_h2, *p_z;
    void *p_wqkv, *p_wproj, *p_w0, *p_w1, *p_bqkv, *p_bproj, *p_b0, *p_b1;
    cudaGetSymbolAddress(&p_h, g_h);
    cudaGetSymbolAddress(&p_qkv, g_qkv);
    cudaGetSymbolAddress(&p_attn, g_attn);
    cudaGetSymbolAddress(&p_res1, g_res1);
    cudaGetSymbolAddress(&p_h2, g_h2);
    cudaGetSymbolAddress(&p_z, g_z);
    cudaGetSymbolAddress(&p_wqkv, g_wqkv);
    cudaGetSymbolAddress(&p_wproj, g_wproj);
    cudaGetSymbolAddress(&p_w0, g_w0);
    cudaGetSymbolAddress(&p_w1, g_w1);
    cudaGetSymbolAddress(&p_bqkv, g_bqkv);
    cudaGetSymbolAddress(&p_bproj, g_bproj);
    cudaGetSymbolAddress(&p_b0, g_b0);
    cudaGetSymbolAddress(&p_b1, g_b1);

    static bool attr_done = false;
    if (!attr_done) {
        cudaFuncSetAttribute(gemm2<EPI_F16>,  cudaFuncAttributeMaxDynamicSharedMemorySize, GEMM_SMEM);
        cudaFuncSetAttribute(gemm2<EPI_GELU>, cudaFuncAttributeMaxDynamicSharedMemorySize, GEMM_SMEM);
        cudaFuncSetAttribute(gemm2<EPI_RES>,  cudaFuncAttributeMaxDynamicSharedMemorySize, GEMM_SMEM);
        attr_done = true;
    }

    auto cast = [&](const float* src, void* dst, int n) {
        int blocks = (n + 255) / 256;
        if (blocks > 4096) blocks = 4096;
        cast_f2h<<<blocks, 256>>>(src, (__half*)dst, n);
    };
    cast(wqkv,  p_wqkv,  E_ * 3 * E_);
    cast(bqkv,  p_bqkv,  3 * E_);
    cast(wproj, p_wproj, E_ * E_);
    cast(bproj, p_bproj, E_);
    cast(w0,    p_w0,    E_ * HID_);
    cast(b0,    p_b0,    HID_);
    cast(w1,    p_w1,    HID_ * E_);
    cast(b1,    p_b1,    E_);

    // LN1
    ln_kernel<<<M_, 256>>>(x, ln1_g, ln1_b, (__half*)p_h);

    // QKV: [8192,1024] @ [1024,3072]
    gemm2<EPI_F16><<<dim3(3 * E_ / 128, M_ / 128), 256, GEMM_SMEM>>>(
        (const __half*)p_h, E_, (const __half*)p_wqkv, 3 * E_,
        (const __half*)p_bqkv, p_qkv, 3 * E_, nullptr, E_);

    // fused flash attention
    flash_attn_kernel<<<dim3(N_ / 128, B_ * H_), 256>>>(
        (const __half*)p_qkv, (__half*)p_attn);

    // proj + residual (fp32 out): res1 = fp16(attn@wproj + bproj) + x
    gemm2<EPI_RES><<<dim3(E_ / 128, M_ / 128), 256, GEMM_SMEM>>>(
        (const __half*)p_attn, E_, (const __half*)p_wproj, E_,
        (const __half*)p_bproj, p_res1, E_, x, E_);

    // LN2
    ln_kernel<<<M_, 256>>>((const float*)p_res1, ln2_g, ln2_b, (__half*)p_h2);

    // MLP up + gelu
    gemm2<EPI_GELU><<<dim3(HID_ / 128, M_ / 128), 256, GEMM_SMEM>>>(
        (const __half*)p_h2, E_, (const __half*)p_w0, HID_,
        (const __half*)p_b0, p_z, HID_, nullptr, E_);

    // MLP down + residual (fp32 out)
    gemm2<EPI_RES><<<dim3(E_ / 128, M_ / 128), 256, GEMM_SMEM>>>(
        (const __half*)p_z, HID_, (const __half*)p_w1, E_,
        (const __half*)p_b1, d_out, E_, (const float*)p_res1, HID_);
}